// round 10
// baseline (speedup 1.0000x reference)
#include <cuda_runtime.h>

// L1Loss: out = mean(|yhat - y|) over 64*128*4096 fp32 elements.
// R10: R9 (LDG.256 .cs streaming + fused single-atomic epilogue) with the
// mainloop unrolled x2 and all four 256-bit loads front-batched (deeper MLP,
// fewer branch/index ops at the now-shallow ~7 trips/thread).

#define NBLOCKS 2368
#define NTHREADS 256
#define FIX_SCALE 1048576.0   // 2^20

__device__ unsigned long long g_pack = 0ull;  // reset by last block each call

struct __align__(32) f8 { float v[8]; };

__device__ __forceinline__ f8 ldcs256(const float* p) {
    f8 r;
    asm volatile(
        "ld.global.cs.v8.f32 {%0,%1,%2,%3,%4,%5,%6,%7}, [%8];"
        : "=f"(r.v[0]), "=f"(r.v[1]), "=f"(r.v[2]), "=f"(r.v[3]),
          "=f"(r.v[4]), "=f"(r.v[5]), "=f"(r.v[6]), "=f"(r.v[7])
        : "l"(p));
    return r;
}

__global__ void __launch_bounds__(NTHREADS) l1_reduce_kernel(
    const float* __restrict__ a,
    const float* __restrict__ b,
    float* __restrict__ out,
    int n8,            // number of float8 groups
    int n_tail,        // scalar elements after n8*8
    float inv_n)
{
    float acc0 = 0.0f, acc1 = 0.0f;

    const int idx    = blockIdx.x * blockDim.x + threadIdx.x;
    const int stride = gridDim.x * blockDim.x;

    int i = idx;
    // Unrolled x2: four LDG.256 front-batched per iteration.
    for (; i + stride < n8; i += 2 * stride) {
        f8 x0 = ldcs256(a + (size_t)i * 8);
        f8 x1 = ldcs256(a + (size_t)(i + stride) * 8);
        f8 y0 = ldcs256(b + (size_t)i * 8);
        f8 y1 = ldcs256(b + (size_t)(i + stride) * 8);
        #pragma unroll
        for (int k = 0; k < 8; k++) acc0 += fabsf(x0.v[k] - y0.v[k]);
        #pragma unroll
        for (int k = 0; k < 8; k++) acc1 += fabsf(x1.v[k] - y1.v[k]);
    }
    for (; i < n8; i += stride) {
        f8 x = ldcs256(a + (size_t)i * 8);
        f8 y = ldcs256(b + (size_t)i * 8);
        #pragma unroll
        for (int k = 0; k < 8; k++) acc0 += fabsf(x.v[k] - y.v[k]);
    }

    // Scalar tail (N not divisible by 8)
    if (blockIdx.x == 0 && threadIdx.x < n_tail) {
        int t = n8 * 8 + threadIdx.x;
        acc0 += fabsf(a[t] - b[t]);
    }

    float acc = acc0 + acc1;

    // Intra-block reduction
    #pragma unroll
    for (int o = 16; o > 0; o >>= 1)
        acc += __shfl_down_sync(0xffffffffu, acc, o);

    __shared__ float smem[NTHREADS / 32];
    int lane = threadIdx.x & 31;
    int wid  = threadIdx.x >> 5;
    if (lane == 0) smem[wid] = acc;
    __syncthreads();
    // Warps 1..7 (and warp 0 lanes 1..31) exit after this point.

    if (threadIdx.x == 0) {
        float v = 0.0f;
        #pragma unroll
        for (int w = 0; w < NTHREADS / 32; w++) v += smem[w];

        // Fixed-point encode: partial in 2^-20 units, count=1 in low 12 bits.
        unsigned long long fixed =
            (unsigned long long)__double2ll_rn((double)v * FIX_SCALE);
        unsigned long long pack = (fixed << 12) | 1ull;

        unsigned long long old = atomicAdd(&g_pack, pack);

        if ((old & 0xFFFull) == (unsigned long long)(NBLOCKS - 1)) {
            // We are the last block; total = old + our contribution.
            unsigned long long total_fixed = (old + pack) >> 12;
            double total = (double)(long long)total_fixed * (1.0 / FIX_SCALE);
            out[0] = (float)(total * (double)inv_n);
            g_pack = 0ull;   // reset for next graph replay (all peers done)
        }
    }
}

extern "C" void kernel_launch(void* const* d_in, const int* in_sizes, int n_in,
                              void* d_out, int out_size)
{
    const float* yhat = (const float*)d_in[0];
    const float* y    = (const float*)d_in[1];
    float* out = (float*)d_out;

    long long n = in_sizes[0];
    int n8 = (int)(n / 8);
    int n_tail = (int)(n - (long long)n8 * 8);
    float inv_n = 1.0f / (float)n;

    l1_reduce_kernel<<<NBLOCKS, NTHREADS>>>(yhat, y, out, n8, n_tail, inv_n);
}

// round 11
// speedup vs baseline: 1.0060x; 1.0060x over previous
#include <cuda_runtime.h>

// L1Loss: out = mean(|yhat - y|) over 64*128*4096 fp32 elements.
// R11: R9 structure exactly (simple grid-stride LDG.256 .cs loop + fused
// single-atomic epilogue), grid 2368 -> 4736 (4 waves) to halve the
// last-wave tail granularity. Ticket field widened to 13 bits.

#define NBLOCKS 4736
#define NTHREADS 256
#define CNT_BITS 13           // 8192 > NBLOCKS
#define CNT_MASK ((1ull << CNT_BITS) - 1ull)
#define FIX_SCALE 1048576.0   // 2^20

__device__ unsigned long long g_pack = 0ull;  // reset by last block each call

struct __align__(32) f8 { float v[8]; };

__device__ __forceinline__ f8 ldcs256(const float* p) {
    f8 r;
    asm volatile(
        "ld.global.cs.v8.f32 {%0,%1,%2,%3,%4,%5,%6,%7}, [%8];"
        : "=f"(r.v[0]), "=f"(r.v[1]), "=f"(r.v[2]), "=f"(r.v[3]),
          "=f"(r.v[4]), "=f"(r.v[5]), "=f"(r.v[6]), "=f"(r.v[7])
        : "l"(p));
    return r;
}

__global__ void __launch_bounds__(NTHREADS) l1_reduce_kernel(
    const float* __restrict__ a,
    const float* __restrict__ b,
    float* __restrict__ out,
    int n8,            // number of float8 groups
    int n_tail,        // scalar elements after n8*8
    float inv_n)
{
    float acc = 0.0f;

    const int idx    = blockIdx.x * blockDim.x + threadIdx.x;
    const int stride = gridDim.x * blockDim.x;

    for (int i = idx; i < n8; i += stride) {
        f8 x = ldcs256(a + (size_t)i * 8);
        f8 y = ldcs256(b + (size_t)i * 8);
        #pragma unroll
        for (int k = 0; k < 8; k++)
            acc += fabsf(x.v[k] - y.v[k]);
    }

    // Scalar tail (N not divisible by 8)
    if (blockIdx.x == 0 && threadIdx.x < n_tail) {
        int t = n8 * 8 + threadIdx.x;
        acc += fabsf(a[t] - b[t]);
    }

    // Intra-block reduction
    #pragma unroll
    for (int o = 16; o > 0; o >>= 1)
        acc += __shfl_down_sync(0xffffffffu, acc, o);

    __shared__ float smem[NTHREADS / 32];
    int lane = threadIdx.x & 31;
    int wid  = threadIdx.x >> 5;
    if (lane == 0) smem[wid] = acc;
    __syncthreads();
    // Warps 1..7 (and warp 0 lanes 1..31) exit after this point.

    if (threadIdx.x == 0) {
        float v = 0.0f;
        #pragma unroll
        for (int w = 0; w < NTHREADS / 32; w++) v += smem[w];

        // Fixed-point encode: partial in 2^-20 units, count=1 in low bits.
        unsigned long long fixed =
            (unsigned long long)__double2ll_rn((double)v * FIX_SCALE);
        unsigned long long pack = (fixed << CNT_BITS) | 1ull;

        unsigned long long old = atomicAdd(&g_pack, pack);

        if ((old & CNT_MASK) == (unsigned long long)(NBLOCKS - 1)) {
            // We are the last block; total = old + our contribution.
            unsigned long long total_fixed = (old + pack) >> CNT_BITS;
            double total = (double)(long long)total_fixed * (1.0 / FIX_SCALE);
            out[0] = (float)(total * (double)inv_n);
            g_pack = 0ull;   // reset for next graph replay (all peers done)
        }
    }
}

extern "C" void kernel_launch(void* const* d_in, const int* in_sizes, int n_in,
                              void* d_out, int out_size)
{
    const float* yhat = (const float*)d_in[0];
    const float* y    = (const float*)d_in[1];
    float* out = (float*)d_out;

    long long n = in_sizes[0];
    int n8 = (int)(n / 8);
    int n_tail = (int)(n - (long long)n8 * 8);
    float inv_n = 1.0f / (float)n;

    l1_reduce_kernel<<<NBLOCKS, NTHREADS>>>(yhat, y, out, n8, n_tail, inv_n);
}